// round 12
// baseline (speedup 1.0000x reference)
#include <cuda_runtime.h>
#include <cuda_fp16.h>
#include <math.h>
#include <stdint.h>

// ---------------- problem constants ----------------
#define BATCH 4
#define SEQ   2048
#define HID   2048
#define NEXP  32
#define INTER 2048
#define TOPK  4
#define NTOK  (BATCH*SEQ)          // 8192
#define NPAIR (NTOK*TOPK)          // 32768
#define MAXTILES (NPAIR/128 + NEXP) // 288

// ---------------- GEMM tiling (fp16, m16n8k16, 4-stage) ----------------
#define BM 128
#define BN 128
#define BK 32                       // fp16: 32 halves = 16 u32 pairs per row
#define STAGES 4
#define PADP 20                     // row stride in u32 pairs (80B) - conflict-free

#define A_STG (BM*PADP)             // 2560 u32
#define B_STG (BN*PADP)             // 2560 u32
#define STG_U32 (A_STG + B_STG)     // 5120 u32 per stage
#define OFF_AROW (STAGES*STG_U32)   // 20480
#define SMEM_U32 (OFF_AROW + BM)
#define SMEM_BYTES (SMEM_U32*4)     // ~80.9 KB -> 2 CTAs/SM

#define NBLK1 (2*INTER/BN)          // 32 n-blocks in GEMM1
#define NSLICES (NEXP*NBLK1)        // 1024 w13 slices

// ---------------- device scratch (static: no allocation allowed) ----------------
__device__ int   g_counts[NEXP];
__device__ int   g_fill[NEXP];
__device__ int   g_offsets[NEXP+1];
__device__ int   g_topk_ids[NPAIR];
__device__ float g_topk_w[NPAIR];
__device__ int   g_perm_token[NPAIR];
__device__ float g_pair_w[NPAIR];
__device__ int   g_pair_pos[NPAIR];
__device__ int   g_tile_expert[MAXTILES];
__device__ int   g_tile_row0[MAXTILES];
__device__ int   g_num_tiles;
__device__ int   g_slice_flag[NSLICES];   // 0=todo, 1=converting, 2=ready

__device__ __half g_xh[(size_t)NTOK*HID];             // x as fp16         (32 MB)
__device__ __half g_w13h[(size_t)NEXP*2*INTER*HID];   // w13 fp16, rows interleaved (512 MB)
__device__ __half g_w2h[(size_t)NEXP*HID*INTER];      // w2 fp16           (256 MB)
__device__ __half g_ih[(size_t)NPAIR*INTER];          // silu(g)*u fp16    (128 MB)
__device__ __half g_pair_out[(size_t)NPAIR*HID];      // per-pair out fp16 (128 MB)

// ---------------- helpers ----------------
__device__ __forceinline__ uint32_t pack2h(float a, float b) {
    __half2 h = __floats2half2_rn(a, b);
    return *(uint32_t*)&h;
}

__device__ __forceinline__ void mma_f16(float* c, const uint32_t* a, const uint32_t* b) {
    asm volatile(
        "mma.sync.aligned.m16n8k16.row.col.f32.f16.f16.f32 "
        "{%0,%1,%2,%3}, {%4,%5,%6,%7}, {%8,%9}, {%0,%1,%2,%3};\n"
        : "+f"(c[0]), "+f"(c[1]), "+f"(c[2]), "+f"(c[3])
        : "r"(a[0]), "r"(a[1]), "r"(a[2]), "r"(a[3]),
          "r"(b[0]), "r"(b[1]));
}

__device__ __forceinline__ void cp16(uint32_t* dst_smem, const void* src_gmem, bool pred) {
    uint32_t s = (uint32_t)__cvta_generic_to_shared(dst_smem);
    int sz = pred ? 16 : 0;  // src_size=0 -> zero-fill 16B
    asm volatile("cp.async.cg.shared.global [%0], [%1], 16, %2;\n"
                 :: "r"(s), "l"(src_gmem), "r"(sz));
}
#define CP_COMMIT() asm volatile("cp.async.commit_group;\n")
#define CP_WAIT2()  asm volatile("cp.async.wait_group 2;\n")

// ---------------- routing ----------------
__global__ void route_kernel(const float* __restrict__ logits) {
    int t = blockIdx.x * blockDim.x + threadIdx.x;
    if (t >= NTOK) return;
    const float* row = logits + (size_t)t * NEXP;

    float v[TOPK]; int id[TOPK];
    #pragma unroll
    for (int k = 0; k < TOPK; k++) { v[k] = -1e30f; id[k] = 0; }

    for (int e = 0; e < NEXP; e++) {
        float x = row[e];
        if (x > v[TOPK-1]) {
            int p = TOPK - 1;
            while (p > 0 && x > v[p-1]) { v[p] = v[p-1]; id[p] = id[p-1]; p--; }
            v[p] = x; id[p] = e;
        }
    }
    float w[TOPK]; float s = 0.f;
    #pragma unroll
    for (int k = 0; k < TOPK; k++) { w[k] = expf(v[k] - v[0]); s += w[k]; }
    float inv = 1.f / s;
    #pragma unroll
    for (int k = 0; k < TOPK; k++) {
        g_topk_ids[t*TOPK + k] = id[k];
        g_topk_w[t*TOPK + k]   = w[k] * inv;
        atomicAdd(&g_counts[id[k]], 1);
    }
}

__global__ void zero_kernel() {
    int i = blockIdx.x * blockDim.x + threadIdx.x;
    if (i < NEXP) { g_counts[i] = 0; g_fill[i] = 0; }
    if (i < NSLICES) g_slice_flag[i] = 0;
}

__global__ void scan_tiles_kernel() {
    if (threadIdx.x != 0) return;
    int off = 0, nt = 0;
    for (int e = 0; e < NEXP; e++) {
        g_offsets[e] = off;
        int c = g_counts[e];
        for (int r = 0; r < c; r += BM) {
            g_tile_expert[nt] = e;
            g_tile_row0[nt]   = off + r;
            nt++;
        }
        off += c;
    }
    g_offsets[NEXP] = off;
    g_num_tiles = nt;
}

__global__ void scatter_kernel() {
    int i = blockIdx.x * blockDim.x + threadIdx.x;
    if (i >= NPAIR) return;
    int e = g_topk_ids[i];
    int pos = g_offsets[e] + atomicAdd(&g_fill[e], 1);
    g_perm_token[pos] = i >> 2;
    g_pair_w[pos]     = g_topk_w[i];
    g_pair_pos[i]     = pos;
}

// ---------------- x -> fp16 (small: 96 MB traffic) ----------------
__global__ void half_x_kernel(const float* __restrict__ src) {
    size_t i = (size_t)blockIdx.x * blockDim.x + threadIdx.x;
    float4 v0 = ((const float4*)src)[2*i];
    float4 v1 = ((const float4*)src)[2*i + 1];
    uint4 o;
    o.x = pack2h(v0.x, v0.y); o.y = pack2h(v0.z, v0.w);
    o.z = pack2h(v1.x, v1.y); o.w = pack2h(v1.z, v1.w);
    ((uint4*)g_xh)[i] = o;
}

// ---------------- grouped NT GEMM (fp16 m16n8k16, fp32 accum, 4-stage) ----------------
// MODE 1: g_ih[pos, j] = fp16(silu(gate)*up), gate/up = gather(g_xh) @ g_w13h[e]^T.
//         w13 slices are converted fp32->fp16 LAZILY inside this kernel via
//         per-slice claim flags (claimant converts; co-sliced CTAs spin briefly).
//         Also moonlights the full w2 fp32->fp16 conversion (consumed by GEMM2).
// MODE 2: g_pair_out[pos, h] = fp16( pair_w[pos] * (g_ih @ g_w2h[e]^T) )
template<int MODE>
__global__ __launch_bounds__(256, 2)
void gemm_nt(const float* __restrict__ w13src, const float* __restrict__ w2src) {
    constexpr int KD = (MODE == 1) ? HID : INTER;   // 2048 both
    constexpr int KT = KD / BK;                     // 64

    int tid = threadIdx.x;

    // ---- moonlighting (MODE 1): w2 fp32 -> fp16 spread over all CTAs ----
    if (MODE == 1) {
        const size_t nchunks = (size_t)NEXP*HID*INTER/8;  // uint4(8 halves) chunks
        size_t cta  = (size_t)blockIdx.x + (size_t)blockIdx.y * gridDim.x;
        size_t ncta = (size_t)gridDim.x * gridDim.y;
        for (size_t i = cta*256 + tid; i < nchunks; i += ncta*256) {
            float4 v0 = ((const float4*)w2src)[2*i];
            float4 v1 = ((const float4*)w2src)[2*i + 1];
            uint4 o;
            o.x = pack2h(v0.x, v0.y); o.y = pack2h(v0.z, v0.w);
            o.z = pack2h(v1.x, v1.y); o.w = pack2h(v1.z, v1.w);
            ((uint4*)g_w2h)[i] = o;
        }
    }

    int tile = blockIdx.x;
    if (tile >= g_num_tiles) return;
    int e    = g_tile_expert[tile];
    int row0 = g_tile_row0[tile];
    int m_valid = g_offsets[e+1] - row0;
    if (m_valid > BM) m_valid = BM;
    int n0 = blockIdx.y * BN;

    extern __shared__ uint32_t smem[];
    int* s_arow = (int*)(smem + OFF_AROW);

    // ---- MODE 1: lazy w13 slice conversion (expert e, rows [n0, n0+BN)) ----
    if (MODE == 1) {
        int sid = e * NBLK1 + blockIdx.y;
        __shared__ int s_state;
        if (tid == 0) s_state = atomicCAS(&g_slice_flag[sid], 0, 1);
        __syncthreads();
        int st = s_state;
        if (st == 0) {
            // claimant: convert this slice (interleaved rows: 2j=gate j, 2j+1=up j)
            const float* W13 = w13src + (size_t)e * (size_t)(2*INTER) * HID;
            __half* dst = g_w13h + ((size_t)e * (2*INTER) + n0) * HID;
            for (int c = tid; c < BN*(HID/8); c += 256) {
                int rl = c >> 8;                // HID/8 = 256 chunks per row
                int cc = c & 255;
                int gr = n0 + rl;
                int j  = gr >> 1;
                int sr = (gr & 1) ? (INTER + j) : j;
                const float4* srow = (const float4*)(W13 + (size_t)sr * HID);
                float4 v0 = srow[2*cc];
                float4 v1 = srow[2*cc + 1];
                uint4 o;
                o.x = pack2h(v0.x, v0.y); o.y = pack2h(v0.z, v0.w);
                o.z = pack2h(v1.x, v1.y); o.w = pack2h(v1.z, v1.w);
                ((uint4*)(dst + (size_t)rl * HID))[cc] = o;
            }
            __threadfence();
            __syncthreads();
            if (tid == 0) atomicExch(&g_slice_flag[sid], 2);
        } else if (st == 1) {
            if (tid == 0) {
                while (atomicAdd(&g_slice_flag[sid], 0) != 2) __nanosleep(100);
            }
            __syncthreads();
            __threadfence();
        } else {
            __threadfence();
        }
    }

    const __half* Ah = (MODE == 1) ? g_xh : g_ih;
    const __half* We = ((MODE == 1) ? g_w13h : g_w2h)
                       + (size_t)e * ((MODE == 1) ? (size_t)2*INTER*KD : (size_t)HID*KD);

    for (int r = tid; r < BM; r += 256) {
        int gr = -1;
        if (r < m_valid) gr = (MODE == 1) ? g_perm_token[row0 + r] : (row0 + r);
        s_arow[r] = gr;
    }
    __syncthreads();

    int wid = tid >> 5, lane = tid & 31;
    int warp_m = wid >> 2, warp_n = wid & 3;       // 2 x 4 warps -> 64x32 warp tiles
    int g = lane >> 2, q = lane & 3;

    float acc[4][4][4];
    #pragma unroll
    for (int a = 0; a < 4; a++)
        #pragma unroll
        for (int b = 0; b < 4; b++)
            #pragma unroll
            for (int c = 0; c < 4; c++) acc[a][b][c] = 0.f;

    // ---- stage loader: A 512 16B-chunks (2/thr), B 512 (2/thr) ----
    auto load_stage = [&](int stage, int kt /*halves*/) {
        uint32_t* Ad = smem + stage*STG_U32;
        uint32_t* Bd = Ad + A_STG;
        #pragma unroll
        for (int i = 0; i < 2; i++) {
            int idx = tid + i*256;
            int r = idx >> 2, c = idx & 3;
            int gr = s_arow[r];
            const __half* src = Ah + (size_t)(gr < 0 ? 0 : gr) * KD + kt + c*8;
            cp16(Ad + r*PADP + c*4, src, gr >= 0);
        }
        #pragma unroll
        for (int i = 0; i < 2; i++) {
            int idx = tid + i*256;
            int r = idx >> 2, c = idx & 3;
            const __half* src = We + (size_t)(n0 + r) * KD + kt + c*8;
            cp16(Bd + r*PADP + c*4, src, true);
        }
        CP_COMMIT();
    };

    load_stage(0, 0);
    load_stage(1, BK);
    load_stage(2, 2*BK);

    for (int it = 0; it < KT; it++) {
        CP_WAIT2();            // <=2 groups outstanding -> stage it%4 arrived
        __syncthreads();       // all warps done with stage (it-1)%4 == (it+3)%4

        int nxt = it + 3;
        if (nxt < KT) load_stage(nxt % STAGES, nxt * BK);
        else CP_COMMIT();      // keep group accounting uniform

        const uint32_t* Ab = smem + (it % STAGES)*STG_U32;
        const uint32_t* Bb = Ab + A_STG;

        #pragma unroll
        for (int kk = 0; kk < 2; kk++) {           // two k16 halves
            int kp = kk * 8;                       // pair offset
            uint32_t af[4][4], bf[4][2];
            #pragma unroll
            for (int mt = 0; mt < 4; mt++) {
                int r = warp_m*64 + mt*16 + g;
                af[mt][0] = Ab[(r    )*PADP + kp + q    ];
                af[mt][1] = Ab[(r + 8)*PADP + kp + q    ];
                af[mt][2] = Ab[(r    )*PADP + kp + q + 4];
                af[mt][3] = Ab[(r + 8)*PADP + kp + q + 4];
            }
            #pragma unroll
            for (int nt = 0; nt < 4; nt++) {
                int bn = warp_n*32 + nt*8 + g;
                bf[nt][0] = Bb[bn*PADP + kp + q    ];
                bf[nt][1] = Bb[bn*PADP + kp + q + 4];
            }
            #pragma unroll
            for (int mt = 0; mt < 4; mt++)
                #pragma unroll
                for (int nt = 0; nt < 4; nt++)
                    mma_f16(acc[mt][nt], af[mt], bf[nt]);
        }
    }

    // ---- epilogue ----
    #pragma unroll
    for (int mt = 0; mt < 4; mt++) {
        #pragma unroll
        for (int h = 0; h < 2; h++) {
            int lr = warp_m*64 + mt*16 + g + h*8;
            if (lr < m_valid) {
                int grow = row0 + lr;
                if (MODE == 1) {
                    // cols (2m,2m+1) = (gate,up) -> inter col m (fp16)
                    __half* dst = g_ih + (size_t)grow * INTER + (n0 >> 1) + warp_n*16;
                    #pragma unroll
                    for (int nt = 0; nt < 4; nt++) {
                        float gv = acc[mt][nt][h*2 + 0];
                        float uv = acc[mt][nt][h*2 + 1];
                        float iv = gv / (1.f + expf(-gv)) * uv;
                        dst[nt*4 + q] = __float2half_rn(iv);
                    }
                } else {
                    float sc = g_pair_w[grow];
                    __half* dst = g_pair_out + (size_t)grow * HID + n0 + warp_n*32;
                    #pragma unroll
                    for (int nt = 0; nt < 4; nt++) {
                        uint32_t packed = pack2h(acc[mt][nt][h*2 + 0] * sc,
                                                 acc[mt][nt][h*2 + 1] * sc);
                        *(uint32_t*)(dst + nt*8 + 2*q) = packed;
                    }
                }
            }
        }
    }
}

// ---------------- deterministic combine (fp16 inputs, fp32 output) ----------------
__global__ void combine_kernel(float* __restrict__ out) {
    int t = blockIdx.x;
    int p0 = g_pair_pos[t*4 + 0];
    int p1 = g_pair_pos[t*4 + 1];
    int p2 = g_pair_pos[t*4 + 2];
    int p3 = g_pair_pos[t*4 + 3];
    const __half2* r0 = (const __half2*)(g_pair_out + (size_t)p0 * HID);
    const __half2* r1 = (const __half2*)(g_pair_out + (size_t)p1 * HID);
    const __half2* r2 = (const __half2*)(g_pair_out + (size_t)p2 * HID);
    const __half2* r3 = (const __half2*)(g_pair_out + (size_t)p3 * HID);
    float2* o = (float2*)(out + (size_t)t * HID);
    for (int c = threadIdx.x; c < HID/2; c += blockDim.x) {
        float2 a = __half22float2(r0[c]);
        float2 b = __half22float2(r1[c]);
        float2 cc = __half22float2(r2[c]);
        float2 d = __half22float2(r3[c]);
        float2 v;
        v.x = a.x + b.x + cc.x + d.x;
        v.y = a.y + b.y + cc.y + d.y;
        o[c] = v;
    }
}

// ---------------- launch ----------------
extern "C" void kernel_launch(void* const* d_in, const int* in_sizes, int n_in,
                              void* d_out, int out_size) {
    const float* x      = (const float*)d_in[0];
    const float* logits = (const float*)d_in[1];
    const float* w13    = (const float*)d_in[2];
    const float* w2     = (const float*)d_in[3];
    float* out = (float*)d_out;

    cudaFuncSetAttribute((const void*)gemm_nt<1>,
                         cudaFuncAttributeMaxDynamicSharedMemorySize, SMEM_BYTES);
    cudaFuncSetAttribute((const void*)gemm_nt<2>,
                         cudaFuncAttributeMaxDynamicSharedMemorySize, SMEM_BYTES);

    zero_kernel<<<(NSLICES + 255)/256, 256>>>();
    route_kernel<<<(NTOK + 255)/256, 256>>>(logits);
    scan_tiles_kernel<<<1, 1>>>();
    scatter_kernel<<<(NPAIR + 255)/256, 256>>>();

    // x -> fp16 (tiny). w13 converted lazily inside GEMM1; w2 moonlighted there.
    half_x_kernel<<<(int)(((size_t)NTOK*HID/8)/256), 256>>>(x);

    gemm_nt<1><<<dim3(MAXTILES, NBLK1), 256, SMEM_BYTES>>>(w13, w2);
    gemm_nt<2><<<dim3(MAXTILES, HID/BN), 256, SMEM_BYTES>>>(nullptr, nullptr);

    combine_kernel<<<NTOK, 128>>>(out);
}

// round 13
// speedup vs baseline: 1.0631x; 1.0631x over previous
#include <cuda_runtime.h>
#include <cuda_fp16.h>
#include <math.h>
#include <stdint.h>

// ---------------- problem constants ----------------
#define BATCH 4
#define SEQ   2048
#define HID   2048
#define NEXP  32
#define INTER 2048
#define TOPK  4
#define NTOK  (BATCH*SEQ)          // 8192
#define NPAIR (NTOK*TOPK)          // 32768
#define MAXTILES (NPAIR/128 + NEXP) // 288

// ---------------- GEMM tiling (fp16, m16n8k16, 4-stage) ----------------
#define BM 128
#define BN 128
#define BK 32                       // fp16: 32 halves = 16 u32 pairs per row
#define STAGES 4
#define PADP 20                     // row stride in u32 pairs (80B) - conflict-free

#define A_STG (BM*PADP)             // 2560 u32
#define B_STG (BN*PADP)             // 2560 u32
#define STG_U32 (A_STG + B_STG)     // 5120 u32 per stage
#define OFF_AROW (STAGES*STG_U32)   // 20480
#define SMEM_U32 (OFF_AROW + BM)
#define SMEM_BYTES (SMEM_U32*4)     // ~80.9 KB -> 2 CTAs/SM

// conversion chunk counts (uint4 = 8 elems)
#define NW13C ((size_t)NEXP*2*INTER*HID/8)   // 33,554,432
#define NXC   ((size_t)NTOK*HID/8)           //  2,097,152

// ---------------- device scratch (static: no allocation allowed) ----------------
__device__ int   g_fill[NEXP];
__device__ int   g_offsets[NEXP+1];
__device__ int   g_topk_ids[NPAIR];
__device__ float g_topk_w[NPAIR];
__device__ int   g_perm_token[NPAIR];
__device__ float g_pair_w[NPAIR];
__device__ int   g_pair_pos[NPAIR];
__device__ int   g_tile_expert[MAXTILES];
__device__ int   g_tile_row0[MAXTILES];
__device__ int   g_num_tiles;

__device__ __half g_xh[(size_t)NTOK*HID];             // x as fp16         (32 MB)
__device__ __half g_w13h[(size_t)NEXP*2*INTER*HID];   // w13 fp16, rows interleaved (512 MB)
__device__ __half g_w2h[(size_t)NEXP*HID*INTER];      // w2 fp16           (256 MB)
__device__ __half g_ih[(size_t)NPAIR*INTER];          // silu(g)*u fp16    (128 MB)
__device__ __half g_pair_out[(size_t)NPAIR*HID];      // per-pair out fp16 (128 MB)

// ---------------- helpers ----------------
__device__ __forceinline__ uint32_t pack2h(float a, float b) {
    __half2 h = __floats2half2_rn(a, b);
    return *(uint32_t*)&h;
}

__device__ __forceinline__ void mma_f16(float* c, const uint32_t* a, const uint32_t* b) {
    asm volatile(
        "mma.sync.aligned.m16n8k16.row.col.f32.f16.f16.f32 "
        "{%0,%1,%2,%3}, {%4,%5,%6,%7}, {%8,%9}, {%0,%1,%2,%3};\n"
        : "+f"(c[0]), "+f"(c[1]), "+f"(c[2]), "+f"(c[3])
        : "r"(a[0]), "r"(a[1]), "r"(a[2]), "r"(a[3]),
          "r"(b[0]), "r"(b[1]));
}

__device__ __forceinline__ void cp16(uint32_t* dst_smem, const void* src_gmem, bool pred) {
    uint32_t s = (uint32_t)__cvta_generic_to_shared(dst_smem);
    int sz = pred ? 16 : 0;  // src_size=0 -> zero-fill 16B
    asm volatile("cp.async.cg.shared.global [%0], [%1], 16, %2;\n"
                 :: "r"(s), "l"(src_gmem), "r"(sz));
}
#define CP_COMMIT() asm volatile("cp.async.commit_group;\n")
#define CP_WAIT2()  asm volatile("cp.async.wait_group 2;\n")

// ---------------- merged kernel: fp16 conversions + routing ----------------
// block 0           : full routing (top-4 + softmax), tile scan, g_fill zeroing
// blocks 1..NW13C/256+...: w13 (gate/up interleaved) and x fp32->fp16 conversion
__global__ void conv_route_kernel(const float* __restrict__ w13,
                                  const float* __restrict__ x,
                                  const float* __restrict__ logits) {
    if (blockIdx.x == 0) {
        __shared__ int s_cnt[NEXP];
        int tid = threadIdx.x;
        if (tid < NEXP) s_cnt[tid] = 0;
        if (tid < NEXP) g_fill[tid] = 0;
        __syncthreads();

        #pragma unroll 1
        for (int k = 0; k < NTOK/256; k++) {
            int t = tid + 256*k;
            const float* row = logits + (size_t)t * NEXP;
            float v[TOPK]; int id[TOPK];
            #pragma unroll
            for (int j = 0; j < TOPK; j++) { v[j] = -1e30f; id[j] = 0; }
            for (int e = 0; e < NEXP; e++) {
                float xv = row[e];
                if (xv > v[TOPK-1]) {
                    int p = TOPK - 1;
                    while (p > 0 && xv > v[p-1]) { v[p] = v[p-1]; id[p] = id[p-1]; p--; }
                    v[p] = xv; id[p] = e;
                }
            }
            float w[TOPK]; float s = 0.f;
            #pragma unroll
            for (int j = 0; j < TOPK; j++) { w[j] = expf(v[j] - v[0]); s += w[j]; }
            float inv = 1.f / s;
            #pragma unroll
            for (int j = 0; j < TOPK; j++) {
                g_topk_ids[t*TOPK + j] = id[j];
                g_topk_w[t*TOPK + j]   = w[j] * inv;
                atomicAdd(&s_cnt[id[j]], 1);
            }
        }
        __syncthreads();
        if (tid == 0) {
            int off = 0, nt = 0;
            for (int e = 0; e < NEXP; e++) {
                g_offsets[e] = off;
                int c = s_cnt[e];
                for (int r = 0; r < c; r += BM) {
                    g_tile_expert[nt] = e;
                    g_tile_row0[nt]   = off + r;
                    nt++;
                }
                off += c;
            }
            g_offsets[NEXP] = off;
            g_num_tiles = nt;
        }
        return;
    }

    size_t i = (size_t)(blockIdx.x - 1) * blockDim.x + threadIdx.x;
    if (i < NW13C) {
        // w13 [E, 2I, H] -> fp16, rows interleaved: dst row 2j = gate j, 2j+1 = up j
        const int ROWC = HID/8;                    // 256 chunks per row
        const size_t PERE = (size_t)(2*INTER) * ROWC;
        size_t e = i / PERE;
        size_t rem = i - e * PERE;
        int r = (int)(rem / ROWC);
        int c = (int)(rem % ROWC);
        int j = r >> 1;
        int srcrow = (r & 1) ? (INTER + j) : j;
        size_t sbase = (e * (size_t)(2*INTER) + srcrow) * ROWC + c;
        float4 v0 = ((const float4*)w13)[2*sbase];
        float4 v1 = ((const float4*)w13)[2*sbase + 1];
        uint4 o;
        o.x = pack2h(v0.x, v0.y); o.y = pack2h(v0.z, v0.w);
        o.z = pack2h(v1.x, v1.y); o.w = pack2h(v1.z, v1.w);
        ((uint4*)g_w13h)[i] = o;
    } else {
        size_t j = i - NW13C;
        if (j < NXC) {
            float4 v0 = ((const float4*)x)[2*j];
            float4 v1 = ((const float4*)x)[2*j + 1];
            uint4 o;
            o.x = pack2h(v0.x, v0.y); o.y = pack2h(v0.z, v0.w);
            o.z = pack2h(v1.x, v1.y); o.w = pack2h(v1.z, v1.w);
            ((uint4*)g_xh)[j] = o;
        }
    }
}

__global__ void scatter_kernel() {
    int i = blockIdx.x * blockDim.x + threadIdx.x;
    if (i >= NPAIR) return;
    int e = g_topk_ids[i];
    int pos = g_offsets[e] + atomicAdd(&g_fill[e], 1);
    g_perm_token[pos] = i >> 2;
    g_pair_w[pos]     = g_topk_w[i];
    g_pair_pos[i]     = pos;
}

// ---------------- grouped NT GEMM (fp16 m16n8k16, fp32 accum, 4-stage) ----------------
// MODE 1: g_ih[pos, j] = fp16(silu(gate)*up), gate/up = gather(g_xh) @ g_w13h[e]^T
//         (w13h rows pre-interleaved: tile row 2j = gate j, 2j+1 = up j)
//         Also moonlights: converts a grid-strided slice of w2 fp32 -> g_w2h.
// MODE 2: g_pair_out[pos, h] = fp16( pair_w[pos] * (g_ih @ g_w2h[e]^T) )
template<int MODE>
__global__ __launch_bounds__(256, 2)
void gemm_nt(const float* __restrict__ w2src) {
    constexpr int KD = (MODE == 1) ? HID : INTER;   // 2048 both
    constexpr int KT = KD / BK;                     // 64

    int tid = threadIdx.x;

    // ---- moonlighting (MODE 1): convert w2 fp32 -> fp16 over all GEMM1 CTAs ----
    if (MODE == 1) {
        const size_t nchunks = (size_t)NEXP*HID*INTER/8;  // uint4(8 halves) chunks
        size_t cta  = (size_t)blockIdx.x + (size_t)blockIdx.y * gridDim.x;
        size_t ncta = (size_t)gridDim.x * gridDim.y;
        for (size_t i = cta*256 + tid; i < nchunks; i += ncta*256) {
            float4 v0 = ((const float4*)w2src)[2*i];
            float4 v1 = ((const float4*)w2src)[2*i + 1];
            uint4 o;
            o.x = pack2h(v0.x, v0.y); o.y = pack2h(v0.z, v0.w);
            o.z = pack2h(v1.x, v1.y); o.w = pack2h(v1.z, v1.w);
            ((uint4*)g_w2h)[i] = o;
        }
    }

    int tile = blockIdx.x;
    if (tile >= g_num_tiles) return;
    int e    = g_tile_expert[tile];
    int row0 = g_tile_row0[tile];
    int m_valid = g_offsets[e+1] - row0;
    if (m_valid > BM) m_valid = BM;
    int n0 = blockIdx.y * BN;

    extern __shared__ uint32_t smem[];
    int* s_arow = (int*)(smem + OFF_AROW);

    const __half* Ah = (MODE == 1) ? g_xh : g_ih;
    const __half* We = ((MODE == 1) ? g_w13h : g_w2h)
                       + (size_t)e * ((MODE == 1) ? (size_t)2*INTER*KD : (size_t)HID*KD);

    for (int r = tid; r < BM; r += 256) {
        int gr = -1;
        if (r < m_valid) gr = (MODE == 1) ? g_perm_token[row0 + r] : (row0 + r);
        s_arow[r] = gr;
    }
    __syncthreads();

    int wid = tid >> 5, lane = tid & 31;
    int warp_m = wid >> 2, warp_n = wid & 3;       // 2 x 4 warps -> 64x32 warp tiles
    int g = lane >> 2, q = lane & 3;

    float acc[4][4][4];
    #pragma unroll
    for (int a = 0; a < 4; a++)
        #pragma unroll
        for (int b = 0; b < 4; b++)
            #pragma unroll
            for (int c = 0; c < 4; c++) acc[a][b][c] = 0.f;

    // ---- stage loader: A 512 16B-chunks (2/thr), B 512 (2/thr) ----
    auto load_stage = [&](int stage, int kt /*halves*/) {
        uint32_t* Ad = smem + stage*STG_U32;
        uint32_t* Bd = Ad + A_STG;
        #pragma unroll
        for (int i = 0; i < 2; i++) {
            int idx = tid + i*256;
            int r = idx >> 2, c = idx & 3;
            int gr = s_arow[r];
            const __half* src = Ah + (size_t)(gr < 0 ? 0 : gr) * KD + kt + c*8;
            cp16(Ad + r*PADP + c*4, src, gr >= 0);
        }
        #pragma unroll
        for (int i = 0; i < 2; i++) {
            int idx = tid + i*256;
            int r = idx >> 2, c = idx & 3;
            const __half* src = We + (size_t)(n0 + r) * KD + kt + c*8;
            cp16(Bd + r*PADP + c*4, src, true);
        }
        CP_COMMIT();
    };

    load_stage(0, 0);
    load_stage(1, BK);
    load_stage(2, 2*BK);

    for (int it = 0; it < KT; it++) {
        CP_WAIT2();            // <=2 groups outstanding -> stage it%4 arrived
        __syncthreads();       // all warps done with stage (it-1)%4 == (it+3)%4

        int nxt = it + 3;
        if (nxt < KT) load_stage(nxt % STAGES, nxt * BK);
        else CP_COMMIT();      // keep group accounting uniform

        const uint32_t* Ab = smem + (it % STAGES)*STG_U32;
        const uint32_t* Bb = Ab + A_STG;

        #pragma unroll
        for (int kk = 0; kk < 2; kk++) {           // two k16 halves
            int kp = kk * 8;                       // pair offset
            uint32_t af[4][4], bf[4][2];
            #pragma unroll
            for (int mt = 0; mt < 4; mt++) {
                int r = warp_m*64 + mt*16 + g;
                af[mt][0] = Ab[(r    )*PADP + kp + q    ];
                af[mt][1] = Ab[(r + 8)*PADP + kp + q    ];
                af[mt][2] = Ab[(r    )*PADP + kp + q + 4];
                af[mt][3] = Ab[(r + 8)*PADP + kp + q + 4];
            }
            #pragma unroll
            for (int nt = 0; nt < 4; nt++) {
                int bn = warp_n*32 + nt*8 + g;
                bf[nt][0] = Bb[bn*PADP + kp + q    ];
                bf[nt][1] = Bb[bn*PADP + kp + q + 4];
            }
            #pragma unroll
            for (int mt = 0; mt < 4; mt++)
                #pragma unroll
                for (int nt = 0; nt < 4; nt++)
                    mma_f16(acc[mt][nt], af[mt], bf[nt]);
        }
    }

    // ---- epilogue ----
    #pragma unroll
    for (int mt = 0; mt < 4; mt++) {
        #pragma unroll
        for (int h = 0; h < 2; h++) {
            int lr = warp_m*64 + mt*16 + g + h*8;
            if (lr < m_valid) {
                int grow = row0 + lr;
                if (MODE == 1) {
                    // cols (2m,2m+1) = (gate,up) -> inter col m (fp16)
                    __half* dst = g_ih + (size_t)grow * INTER + (n0 >> 1) + warp_n*16;
                    #pragma unroll
                    for (int nt = 0; nt < 4; nt++) {
                        float gv = acc[mt][nt][h*2 + 0];
                        float uv = acc[mt][nt][h*2 + 1];
                        float iv = gv / (1.f + expf(-gv)) * uv;
                        dst[nt*4 + q] = __float2half_rn(iv);
                    }
                } else {
                    float sc = g_pair_w[grow];
                    __half* dst = g_pair_out + (size_t)grow * HID + n0 + warp_n*32;
                    #pragma unroll
                    for (int nt = 0; nt < 4; nt++) {
                        uint32_t packed = pack2h(acc[mt][nt][h*2 + 0] * sc,
                                                 acc[mt][nt][h*2 + 1] * sc);
                        *(uint32_t*)(dst + nt*8 + 2*q) = packed;
                    }
                }
            }
        }
    }
}

// ---------------- deterministic combine (fp16 inputs, fp32 output) ----------------
__global__ void combine_kernel(float* __restrict__ out) {
    int t = blockIdx.x;
    int p0 = g_pair_pos[t*4 + 0];
    int p1 = g_pair_pos[t*4 + 1];
    int p2 = g_pair_pos[t*4 + 2];
    int p3 = g_pair_pos[t*4 + 3];
    const __half2* r0 = (const __half2*)(g_pair_out + (size_t)p0 * HID);
    const __half2* r1 = (const __half2*)(g_pair_out + (size_t)p1 * HID);
    const __half2* r2 = (const __half2*)(g_pair_out + (size_t)p2 * HID);
    const __half2* r3 = (const __half2*)(g_pair_out + (size_t)p3 * HID);
    float2* o = (float2*)(out + (size_t)t * HID);
    for (int c = threadIdx.x; c < HID/2; c += blockDim.x) {
        float2 a = __half22float2(r0[c]);
        float2 b = __half22float2(r1[c]);
        float2 cc = __half22float2(r2[c]);
        float2 d = __half22float2(r3[c]);
        float2 v;
        v.x = a.x + b.x + cc.x + d.x;
        v.y = a.y + b.y + cc.y + d.y;
        o[c] = v;
    }
}

// ---------------- launch ----------------
extern "C" void kernel_launch(void* const* d_in, const int* in_sizes, int n_in,
                              void* d_out, int out_size) {
    const float* x      = (const float*)d_in[0];
    const float* logits = (const float*)d_in[1];
    const float* w13    = (const float*)d_in[2];
    const float* w2     = (const float*)d_in[3];
    float* out = (float*)d_out;

    cudaFuncSetAttribute((const void*)gemm_nt<1>,
                         cudaFuncAttributeMaxDynamicSharedMemorySize, SMEM_BYTES);
    cudaFuncSetAttribute((const void*)gemm_nt<2>,
                         cudaFuncAttributeMaxDynamicSharedMemorySize, SMEM_BYTES);

    // merged: w13+x fp16 conversion (blocks 1..N) + routing/scan (block 0)
    {
        size_t total = NW13C + NXC;
        int blocks = (int)((total + 255)/256) + 1;
        conv_route_kernel<<<blocks, 256>>>(w13, x, logits);
    }
    scatter_kernel<<<(NPAIR + 255)/256, 256>>>();

    gemm_nt<1><<<dim3(MAXTILES, (2*INTER)/BN), 256, SMEM_BYTES>>>(w2);
    gemm_nt<2><<<dim3(MAXTILES, HID/BN), 256, SMEM_BYTES>>>(nullptr);

    combine_kernel<<<NTOK, 128>>>(out);
}

// round 14
// speedup vs baseline: 1.3005x; 1.2234x over previous
#include <cuda_runtime.h>
#include <cuda_fp16.h>
#include <math.h>
#include <stdint.h>

// ---------------- problem constants ----------------
#define BATCH 4
#define SEQ   2048
#define HID   2048
#define NEXP  32
#define INTER 2048
#define TOPK  4
#define NTOK  (BATCH*SEQ)          // 8192
#define NPAIR (NTOK*TOPK)          // 32768
#define MAXTILES (NPAIR/128 + NEXP) // 288

// ---------------- GEMM tiling (fp16, m16n8k16, 4-stage) ----------------
#define BM 128
#define BN 128
#define BK 32                       // fp16: 32 halves = 16 u32 pairs per row
#define STAGES 4
#define PADP 20                     // row stride in u32 pairs (80B) - conflict-free

#define A_STG (BM*PADP)             // 2560 u32
#define B_STG (BN*PADP)             // 2560 u32
#define STG_U32 (A_STG + B_STG)     // 5120 u32 per stage
#define OFF_AROW (STAGES*STG_U32)   // 20480
#define SMEM_U32 (OFF_AROW + BM)
#define SMEM_BYTES (SMEM_U32*4)     // ~80.9 KB -> 2 CTAs/SM

// conversion chunk counts (uint4 = 8 elems)
#define NW13C ((size_t)NEXP*2*INTER*HID/8)   // 33,554,432
#define NXC   ((size_t)NTOK*HID/8)           //  2,097,152

// ---------------- device scratch (static: no allocation allowed) ----------------
__device__ int   g_counts[NEXP];
__device__ int   g_fill[NEXP];
__device__ int   g_offsets[NEXP+1];
__device__ int   g_topk_ids[NPAIR];
__device__ float g_topk_w[NPAIR];
__device__ int   g_perm_token[NPAIR];
__device__ float g_pair_w[NPAIR];
__device__ int   g_pair_pos[NPAIR];
__device__ int   g_tile_expert[MAXTILES];
__device__ int   g_tile_row0[MAXTILES];
__device__ int   g_num_tiles;

__device__ __half g_xh[(size_t)NTOK*HID];             // x as fp16         (32 MB)
__device__ __half g_w13h[(size_t)NEXP*2*INTER*HID];   // w13 fp16, rows interleaved (512 MB)
__device__ __half g_w2h[(size_t)NEXP*HID*INTER];      // w2 fp16           (256 MB)
__device__ __half g_ih[(size_t)NPAIR*INTER];          // silu(g)*u fp16    (128 MB)
__device__ __half g_pair_out[(size_t)NPAIR*HID];      // per-pair out fp16 (128 MB)

// ---------------- helpers ----------------
__device__ __forceinline__ uint32_t pack2h(float a, float b) {
    __half2 h = __floats2half2_rn(a, b);
    return *(uint32_t*)&h;
}

__device__ __forceinline__ void mma_f16(float* c, const uint32_t* a, const uint32_t* b) {
    asm volatile(
        "mma.sync.aligned.m16n8k16.row.col.f32.f16.f16.f32 "
        "{%0,%1,%2,%3}, {%4,%5,%6,%7}, {%8,%9}, {%0,%1,%2,%3};\n"
        : "+f"(c[0]), "+f"(c[1]), "+f"(c[2]), "+f"(c[3])
        : "r"(a[0]), "r"(a[1]), "r"(a[2]), "r"(a[3]),
          "r"(b[0]), "r"(b[1]));
}

__device__ __forceinline__ void ldsm4(uint32_t* r, uint32_t addr) {
    asm volatile("ldmatrix.sync.aligned.m8n8.x4.shared.b16 {%0,%1,%2,%3}, [%4];"
        : "=r"(r[0]), "=r"(r[1]), "=r"(r[2]), "=r"(r[3]) : "r"(addr));
}

__device__ __forceinline__ void cp16(uint32_t* dst_smem, const void* src_gmem, bool pred) {
    uint32_t s = (uint32_t)__cvta_generic_to_shared(dst_smem);
    int sz = pred ? 16 : 0;  // src_size=0 -> zero-fill 16B
    asm volatile("cp.async.cg.shared.global [%0], [%1], 16, %2;\n"
                 :: "r"(s), "l"(src_gmem), "r"(sz));
}
#define CP_COMMIT() asm volatile("cp.async.commit_group;\n")
#define CP_WAIT2()  asm volatile("cp.async.wait_group 2;\n")

// ---------------- routing ----------------
__global__ void route_kernel(const float* __restrict__ logits) {
    int t = blockIdx.x * blockDim.x + threadIdx.x;
    if (t >= NTOK) return;
    const float* row = logits + (size_t)t * NEXP;

    float v[TOPK]; int id[TOPK];
    #pragma unroll
    for (int k = 0; k < TOPK; k++) { v[k] = -1e30f; id[k] = 0; }

    for (int e = 0; e < NEXP; e++) {
        float x = row[e];
        if (x > v[TOPK-1]) {
            int p = TOPK - 1;
            while (p > 0 && x > v[p-1]) { v[p] = v[p-1]; id[p] = id[p-1]; p--; }
            v[p] = x; id[p] = e;
        }
    }
    float w[TOPK]; float s = 0.f;
    #pragma unroll
    for (int k = 0; k < TOPK; k++) { w[k] = expf(v[k] - v[0]); s += w[k]; }
    float inv = 1.f / s;
    #pragma unroll
    for (int k = 0; k < TOPK; k++) {
        g_topk_ids[t*TOPK + k] = id[k];
        g_topk_w[t*TOPK + k]   = w[k] * inv;
        atomicAdd(&g_counts[id[k]], 1);
    }
}

__global__ void zero_kernel() {
    int i = threadIdx.x;
    if (i < NEXP) { g_counts[i] = 0; g_fill[i] = 0; }
}

__global__ void scan_tiles_kernel() {
    if (threadIdx.x != 0) return;
    int off = 0, nt = 0;
    for (int e = 0; e < NEXP; e++) {
        g_offsets[e] = off;
        int c = g_counts[e];
        for (int r = 0; r < c; r += BM) {
            g_tile_expert[nt] = e;
            g_tile_row0[nt]   = off + r;
            nt++;
        }
        off += c;
    }
    g_offsets[NEXP] = off;
    g_num_tiles = nt;
}

__global__ void scatter_kernel() {
    int i = blockIdx.x * blockDim.x + threadIdx.x;
    if (i >= NPAIR) return;
    int e = g_topk_ids[i];
    int pos = g_offsets[e] + atomicAdd(&g_fill[e], 1);
    g_perm_token[pos] = i >> 2;
    g_pair_w[pos]     = g_topk_w[i];
    g_pair_pos[i]     = pos;
}

// ---------------- merged fp16 conversion: w13 (interleaved) + x ----------------
__global__ void half_conv_kernel(const float* __restrict__ w13,
                                 const float* __restrict__ x) {
    size_t i = (size_t)blockIdx.x * blockDim.x + threadIdx.x;
    if (i < NW13C) {
        // w13 [E, 2I, H] -> fp16, rows interleaved: dst row 2j = gate j, 2j+1 = up j
        const int ROWC = HID/8;                    // 256 chunks per row
        const size_t PERE = (size_t)(2*INTER) * ROWC;
        size_t e = i / PERE;
        size_t rem = i - e * PERE;
        int r = (int)(rem / ROWC);
        int c = (int)(rem % ROWC);
        int j = r >> 1;
        int srcrow = (r & 1) ? (INTER + j) : j;
        size_t sbase = (e * (size_t)(2*INTER) + srcrow) * ROWC + c;
        float4 v0 = ((const float4*)w13)[2*sbase];
        float4 v1 = ((const float4*)w13)[2*sbase + 1];
        uint4 o;
        o.x = pack2h(v0.x, v0.y); o.y = pack2h(v0.z, v0.w);
        o.z = pack2h(v1.x, v1.y); o.w = pack2h(v1.z, v1.w);
        ((uint4*)g_w13h)[i] = o;
    } else {
        size_t j = i - NW13C;
        if (j < NXC) {
            float4 v0 = ((const float4*)x)[2*j];
            float4 v1 = ((const float4*)x)[2*j + 1];
            uint4 o;
            o.x = pack2h(v0.x, v0.y); o.y = pack2h(v0.z, v0.w);
            o.z = pack2h(v1.x, v1.y); o.w = pack2h(v1.z, v1.w);
            ((uint4*)g_xh)[j] = o;
        }
    }
}

// ---------------- grouped NT GEMM (fp16 m16n8k16, fp32 accum, 4-stage, ldmatrix) ----
// MODE 1: g_ih[pos, j] = fp16(silu(gate)*up), gate/up = gather(g_xh) @ g_w13h[e]^T
//         (w13h rows pre-interleaved: tile row 2j = gate j, 2j+1 = up j)
//         Also moonlights: converts a grid-strided slice of w2 fp32 -> g_w2h.
// MODE 2: g_pair_out[pos, h] = fp16( pair_w[pos] * (g_ih @ g_w2h[e]^T) )
template<int MODE>
__global__ __launch_bounds__(256, 2)
void gemm_nt(const float* __restrict__ w2src) {
    constexpr int KD = (MODE == 1) ? HID : INTER;   // 2048 both
    constexpr int KT = KD / BK;                     // 64

    int tid = threadIdx.x;

    // ---- moonlighting (MODE 1): convert w2 fp32 -> fp16 over all GEMM1 CTAs ----
    if (MODE == 1) {
        const size_t nchunks = (size_t)NEXP*HID*INTER/8;  // uint4(8 halves) chunks
        size_t cta  = (size_t)blockIdx.x + (size_t)blockIdx.y * gridDim.x;
        size_t ncta = (size_t)gridDim.x * gridDim.y;
        for (size_t i = cta*256 + tid; i < nchunks; i += ncta*256) {
            float4 v0 = ((const float4*)w2src)[2*i];
            float4 v1 = ((const float4*)w2src)[2*i + 1];
            uint4 o;
            o.x = pack2h(v0.x, v0.y); o.y = pack2h(v0.z, v0.w);
            o.z = pack2h(v1.x, v1.y); o.w = pack2h(v1.z, v1.w);
            ((uint4*)g_w2h)[i] = o;
        }
    }

    int tile = blockIdx.x;
    if (tile >= g_num_tiles) return;
    int e    = g_tile_expert[tile];
    int row0 = g_tile_row0[tile];
    int m_valid = g_offsets[e+1] - row0;
    if (m_valid > BM) m_valid = BM;
    int n0 = blockIdx.y * BN;

    extern __shared__ uint32_t smem[];
    int* s_arow = (int*)(smem + OFF_AROW);

    const __half* Ah = (MODE == 1) ? g_xh : g_ih;
    const __half* We = ((MODE == 1) ? g_w13h : g_w2h)
                       + (size_t)e * ((MODE == 1) ? (size_t)2*INTER*KD : (size_t)HID*KD);

    for (int r = tid; r < BM; r += 256) {
        int gr = -1;
        if (r < m_valid) gr = (MODE == 1) ? g_perm_token[row0 + r] : (row0 + r);
        s_arow[r] = gr;
    }
    __syncthreads();

    int wid = tid >> 5, lane = tid & 31;
    int warp_m = wid >> 2, warp_n = wid & 3;       // 2 x 4 warps -> 64x32 warp tiles
    int g = lane >> 2, q = lane & 3;

    // ldmatrix per-lane invariant byte offsets (within a stage)
    int sub = lane & 7, sel = lane >> 3;
    uint32_t a_inv = (uint32_t)((warp_m*64 + (sel & 1)*8 + sub) * (PADP*4)
                                + (sel >> 1) * 16);
    uint32_t b_inv = (uint32_t)(A_STG*4
                                + (warp_n*32 + (sel >> 1)*8 + sub) * (PADP*4)
                                + (sel & 1) * 16);
    uint32_t smem_sb = (uint32_t)__cvta_generic_to_shared(smem);

    float acc[4][4][4];
    #pragma unroll
    for (int a = 0; a < 4; a++)
        #pragma unroll
        for (int b = 0; b < 4; b++)
            #pragma unroll
            for (int c = 0; c < 4; c++) acc[a][b][c] = 0.f;

    // ---- stage loader: A 512 16B-chunks (2/thr), B 512 (2/thr) ----
    auto load_stage = [&](int stage, int kt /*halves*/) {
        uint32_t* Ad = smem + stage*STG_U32;
        uint32_t* Bd = Ad + A_STG;
        #pragma unroll
        for (int i = 0; i < 2; i++) {
            int idx = tid + i*256;
            int r = idx >> 2, c = idx & 3;
            int gr = s_arow[r];
            const __half* src = Ah + (size_t)(gr < 0 ? 0 : gr) * KD + kt + c*8;
            cp16(Ad + r*PADP + c*4, src, gr >= 0);
        }
        #pragma unroll
        for (int i = 0; i < 2; i++) {
            int idx = tid + i*256;
            int r = idx >> 2, c = idx & 3;
            const __half* src = We + (size_t)(n0 + r) * KD + kt + c*8;
            cp16(Bd + r*PADP + c*4, src, true);
        }
        CP_COMMIT();
    };

    load_stage(0, 0);
    load_stage(1, BK);
    load_stage(2, 2*BK);

    for (int it = 0; it < KT; it++) {
        CP_WAIT2();            // <=2 groups outstanding -> stage it%4 arrived
        __syncthreads();       // all warps done with stage (it-1)%4 == (it+3)%4

        int nxt = it + 3;
        if (nxt < KT) load_stage(nxt % STAGES, nxt * BK);
        else CP_COMMIT();      // keep group accounting uniform

        uint32_t sb = smem_sb + (uint32_t)((it % STAGES) * (STG_U32*4));
        uint32_t a_base = sb + a_inv;
        uint32_t b_base = sb + b_inv;

        #pragma unroll
        for (int kk = 0; kk < 2; kk++) {           // two k16 halves
            uint32_t af[4][4], bf[4][2];
            #pragma unroll
            for (int mt = 0; mt < 4; mt++)
                ldsm4(af[mt], a_base + mt*(16*PADP*4) + kk*32);
            #pragma unroll
            for (int p = 0; p < 2; p++) {
                uint32_t r4[4];
                ldsm4(r4, b_base + p*(16*PADP*4) + kk*32);
                bf[2*p  ][0] = r4[0]; bf[2*p  ][1] = r4[1];
                bf[2*p+1][0] = r4[2]; bf[2*p+1][1] = r4[3];
            }
            #pragma unroll
            for (int mt = 0; mt < 4; mt++)
                #pragma unroll
                for (int nt = 0; nt < 4; nt++)
                    mma_f16(acc[mt][nt], af[mt], bf[nt]);
        }
    }

    // ---- epilogue ----
    #pragma unroll
    for (int mt = 0; mt < 4; mt++) {
        #pragma unroll
        for (int h = 0; h < 2; h++) {
            int lr = warp_m*64 + mt*16 + g + h*8;
            if (lr < m_valid) {
                int grow = row0 + lr;
                if (MODE == 1) {
                    // cols (2m,2m+1) = (gate,up) -> inter col m (fp16)
                    __half* dst = g_ih + (size_t)grow * INTER + (n0 >> 1) + warp_n*16;
                    #pragma unroll
                    for (int nt = 0; nt < 4; nt++) {
                        float gv = acc[mt][nt][h*2 + 0];
                        float uv = acc[mt][nt][h*2 + 1];
                        float iv = gv / (1.f + expf(-gv)) * uv;
                        dst[nt*4 + q] = __float2half_rn(iv);
                    }
                } else {
                    float sc = g_pair_w[grow];
                    __half* dst = g_pair_out + (size_t)grow * HID + n0 + warp_n*32;
                    #pragma unroll
                    for (int nt = 0; nt < 4; nt++) {
                        uint32_t packed = pack2h(acc[mt][nt][h*2 + 0] * sc,
                                                 acc[mt][nt][h*2 + 1] * sc);
                        *(uint32_t*)(dst + nt*8 + 2*q) = packed;
                    }
                }
            }
        }
    }
}

// ---------------- deterministic combine (fp16 inputs, fp32 output) ----------------
__global__ void combine_kernel(float* __restrict__ out) {
    int t = blockIdx.x;
    int p0 = g_pair_pos[t*4 + 0];
    int p1 = g_pair_pos[t*4 + 1];
    int p2 = g_pair_pos[t*4 + 2];
    int p3 = g_pair_pos[t*4 + 3];
    const __half2* r0 = (const __half2*)(g_pair_out + (size_t)p0 * HID);
    const __half2* r1 = (const __half2*)(g_pair_out + (size_t)p1 * HID);
    const __half2* r2 = (const __half2*)(g_pair_out + (size_t)p2 * HID);
    const __half2* r3 = (const __half2*)(g_pair_out + (size_t)p3 * HID);
    float2* o = (float2*)(out + (size_t)t * HID);
    for (int c = threadIdx.x; c < HID/2; c += blockDim.x) {
        float2 a = __half22float2(r0[c]);
        float2 b = __half22float2(r1[c]);
        float2 cc = __half22float2(r2[c]);
        float2 d = __half22float2(r3[c]);
        float2 v;
        v.x = a.x + b.x + cc.x + d.x;
        v.y = a.y + b.y + cc.y + d.y;
        o[c] = v;
    }
}

// ---------------- launch ----------------
extern "C" void kernel_launch(void* const* d_in, const int* in_sizes, int n_in,
                              void* d_out, int out_size) {
    const float* x      = (const float*)d_in[0];
    const float* logits = (const float*)d_in[1];
    const float* w13    = (const float*)d_in[2];
    const float* w2     = (const float*)d_in[3];
    float* out = (float*)d_out;

    cudaFuncSetAttribute((const void*)gemm_nt<1>,
                         cudaFuncAttributeMaxDynamicSharedMemorySize, SMEM_BYTES);
    cudaFuncSetAttribute((const void*)gemm_nt<2>,
                         cudaFuncAttributeMaxDynamicSharedMemorySize, SMEM_BYTES);

    zero_kernel<<<1, 32>>>();
    route_kernel<<<(NTOK + 255)/256, 256>>>(logits);
    scan_tiles_kernel<<<1, 1>>>();
    scatter_kernel<<<(NPAIR + 255)/256, 256>>>();

    // merged fp16 conversions: w13 (interleaved) + x. w2 moonlighted in GEMM1.
    {
        size_t total = NW13C + NXC;
        half_conv_kernel<<<(int)((total + 255)/256), 256>>>(w13, x);
    }

    gemm_nt<1><<<dim3(MAXTILES, (2*INTER)/BN), 256, SMEM_BYTES>>>(w2);
    gemm_nt<2><<<dim3(MAXTILES, HID/BN), 256, SMEM_BYTES>>>(nullptr);

    combine_kernel<<<NTOK, 128>>>(out);
}

// round 15
// speedup vs baseline: 1.3032x; 1.0020x over previous
#include <cuda_runtime.h>
#include <cuda_fp16.h>
#include <math.h>
#include <stdint.h>

// ---------------- problem constants ----------------
#define BATCH 4
#define SEQ   2048
#define HID   2048
#define NEXP  32
#define INTER 2048
#define TOPK  4
#define NTOK  (BATCH*SEQ)          // 8192
#define NPAIR (NTOK*TOPK)          // 32768
#define MAXTILES (NPAIR/128 + NEXP) // 288

// ---------------- GEMM tiling (fp16, m16n8k16, 4-stage) ----------------
#define BM 128
#define BN 128
#define BK 32                       // fp16: 32 halves = 16 u32 pairs per row
#define STAGES 4
#define PADP 20                     // row stride in u32 pairs (80B) - conflict-free

#define A_STG (BM*PADP)             // 2560 u32
#define B_STG (BN*PADP)             // 2560 u32
#define STG_U32 (A_STG + B_STG)     // 5120 u32 per stage
#define OFF_AROW (STAGES*STG_U32)   // 20480
#define SMEM_U32 (OFF_AROW + BM)
#define SMEM_BYTES (SMEM_U32*4)     // ~80.9 KB -> 2 CTAs/SM

// conversion chunk counts (uint4 = 8 elems)
#define NW13C ((size_t)NEXP*2*INTER*HID/8)   // 33,554,432
#define NXC   ((size_t)NTOK*HID/8)           //  2,097,152

// ---------------- device scratch (static: no allocation allowed) ----------------
__device__ int   g_counts[NEXP];
__device__ int   g_fill[NEXP];
__device__ int   g_offsets[NEXP+1];
__device__ int   g_topk_ids[NPAIR];
__device__ float g_topk_w[NPAIR];
__device__ int   g_perm_token[NPAIR];
__device__ float g_pair_w[NPAIR];
__device__ int   g_pair_pos[NPAIR];
__device__ int   g_tile_expert[MAXTILES];
__device__ int   g_tile_row0[MAXTILES];
__device__ int   g_num_tiles;

__device__ __half g_xh[(size_t)NTOK*HID];             // x as fp16         (32 MB)
__device__ __half g_w13h[(size_t)NEXP*2*INTER*HID];   // w13 fp16, rows interleaved (512 MB)
__device__ __half g_w2h[(size_t)NEXP*HID*INTER];      // w2 fp16           (256 MB)
__device__ __half g_ih[(size_t)NPAIR*INTER];          // silu(g)*u fp16    (128 MB)
__device__ __half g_pair_out[(size_t)NPAIR*HID];      // per-pair out fp16 (128 MB)

// ---------------- helpers ----------------
__device__ __forceinline__ uint32_t pack2h(float a, float b) {
    __half2 h = __floats2half2_rn(a, b);
    return *(uint32_t*)&h;
}

__device__ __forceinline__ void mma_f16(float* c, const uint32_t* a, const uint32_t* b) {
    asm volatile(
        "mma.sync.aligned.m16n8k16.row.col.f32.f16.f16.f32 "
        "{%0,%1,%2,%3}, {%4,%5,%6,%7}, {%8,%9}, {%0,%1,%2,%3};\n"
        : "+f"(c[0]), "+f"(c[1]), "+f"(c[2]), "+f"(c[3])
        : "r"(a[0]), "r"(a[1]), "r"(a[2]), "r"(a[3]),
          "r"(b[0]), "r"(b[1]));
}

__device__ __forceinline__ void ldsm4(uint32_t* r, uint32_t addr) {
    asm volatile("ldmatrix.sync.aligned.m8n8.x4.shared.b16 {%0,%1,%2,%3}, [%4];"
        : "=r"(r[0]), "=r"(r[1]), "=r"(r[2]), "=r"(r[3]) : "r"(addr));
}

__device__ __forceinline__ void cp16(uint32_t* dst_smem, const void* src_gmem, bool pred) {
    uint32_t s = (uint32_t)__cvta_generic_to_shared(dst_smem);
    int sz = pred ? 16 : 0;  // src_size=0 -> zero-fill 16B
    asm volatile("cp.async.cg.shared.global [%0], [%1], 16, %2;\n"
                 :: "r"(s), "l"(src_gmem), "r"(sz));
}
#define CP_COMMIT() asm volatile("cp.async.commit_group;\n")
#define CP_WAIT2()  asm volatile("cp.async.wait_group 2;\n")

// ---------------- routing ----------------
__global__ void route_kernel(const float* __restrict__ logits) {
    int t = blockIdx.x * blockDim.x + threadIdx.x;
    if (t >= NTOK) return;
    const float* row = logits + (size_t)t * NEXP;

    float v[TOPK]; int id[TOPK];
    #pragma unroll
    for (int k = 0; k < TOPK; k++) { v[k] = -1e30f; id[k] = 0; }

    for (int e = 0; e < NEXP; e++) {
        float x = row[e];
        if (x > v[TOPK-1]) {
            int p = TOPK - 1;
            while (p > 0 && x > v[p-1]) { v[p] = v[p-1]; id[p] = id[p-1]; p--; }
            v[p] = x; id[p] = e;
        }
    }
    float w[TOPK]; float s = 0.f;
    #pragma unroll
    for (int k = 0; k < TOPK; k++) { w[k] = expf(v[k] - v[0]); s += w[k]; }
    float inv = 1.f / s;
    #pragma unroll
    for (int k = 0; k < TOPK; k++) {
        g_topk_ids[t*TOPK + k] = id[k];
        g_topk_w[t*TOPK + k]   = w[k] * inv;
        atomicAdd(&g_counts[id[k]], 1);
    }
}

__global__ void zero_kernel() {
    int i = threadIdx.x;
    if (i < NEXP) { g_counts[i] = 0; g_fill[i] = 0; }
}

__global__ void scan_tiles_kernel() {
    if (threadIdx.x != 0) return;
    int off = 0, nt = 0;
    for (int e = 0; e < NEXP; e++) {
        g_offsets[e] = off;
        int c = g_counts[e];
        for (int r = 0; r < c; r += BM) {
            g_tile_expert[nt] = e;
            g_tile_row0[nt]   = off + r;
            nt++;
        }
        off += c;
    }
    g_offsets[NEXP] = off;
    g_num_tiles = nt;
}

__global__ void scatter_kernel() {
    int i = blockIdx.x * blockDim.x + threadIdx.x;
    if (i >= NPAIR) return;
    int e = g_topk_ids[i];
    int pos = g_offsets[e] + atomicAdd(&g_fill[e], 1);
    g_perm_token[pos] = i >> 2;
    g_pair_w[pos]     = g_topk_w[i];
    g_pair_pos[i]     = pos;
}

// ---------------- merged fp16 conversion: w13 (interleaved) + x ----------------
__global__ void half_conv_kernel(const float* __restrict__ w13,
                                 const float* __restrict__ x) {
    size_t i = (size_t)blockIdx.x * blockDim.x + threadIdx.x;
    if (i < NW13C) {
        // w13 [E, 2I, H] -> fp16, rows interleaved: dst row 2j = gate j, 2j+1 = up j
        const int ROWC = HID/8;                    // 256 chunks per row
        const size_t PERE = (size_t)(2*INTER) * ROWC;
        size_t e = i / PERE;
        size_t rem = i - e * PERE;
        int r = (int)(rem / ROWC);
        int c = (int)(rem % ROWC);
        int j = r >> 1;
        int srcrow = (r & 1) ? (INTER + j) : j;
        size_t sbase = (e * (size_t)(2*INTER) + srcrow) * ROWC + c;
        float4 v0 = ((const float4*)w13)[2*sbase];
        float4 v1 = ((const float4*)w13)[2*sbase + 1];
        uint4 o;
        o.x = pack2h(v0.x, v0.y); o.y = pack2h(v0.z, v0.w);
        o.z = pack2h(v1.x, v1.y); o.w = pack2h(v1.z, v1.w);
        ((uint4*)g_w13h)[i] = o;
    } else {
        size_t j = i - NW13C;
        if (j < NXC) {
            float4 v0 = ((const float4*)x)[2*j];
            float4 v1 = ((const float4*)x)[2*j + 1];
            uint4 o;
            o.x = pack2h(v0.x, v0.y); o.y = pack2h(v0.z, v0.w);
            o.z = pack2h(v1.x, v1.y); o.w = pack2h(v1.z, v1.w);
            ((uint4*)g_xh)[j] = o;
        }
    }
}

// ---------------- grouped NT GEMM (fp16 m16n8k16, fp32 accum, 4-stage, ldmatrix) ----
// MODE 1: g_ih[pos, j] = fp16(silu(gate)*up), gate/up = gather(g_xh) @ g_w13h[e]^T
//         grid (x=tile, y=nblk): adjacent CTAs share the B slice (w13h 512MB).
//         Also moonlights: converts a grid-strided slice of w2 fp32 -> g_w2h.
// MODE 2: g_pair_out[pos, h] = fp16( pair_w[pos] * (g_ih @ g_w2h[e]^T) )
//         grid (x=nblk, y=tile): adjacent CTAs share the A tile so the 128MB
//         g_ih is read ~once from DRAM instead of 16x (L2 can't hold it).
template<int MODE>
__global__ __launch_bounds__(256, 2)
void gemm_nt(const float* __restrict__ w2src) {
    constexpr int KD = (MODE == 1) ? HID : INTER;   // 2048 both
    constexpr int KT = KD / BK;                     // 64

    int tid = threadIdx.x;

    // ---- moonlighting (MODE 1): convert w2 fp32 -> fp16 over all GEMM1 CTAs ----
    if (MODE == 1) {
        const size_t nchunks = (size_t)NEXP*HID*INTER/8;  // uint4(8 halves) chunks
        size_t cta  = (size_t)blockIdx.x + (size_t)blockIdx.y * gridDim.x;
        size_t ncta = (size_t)gridDim.x * gridDim.y;
        for (size_t i = cta*256 + tid; i < nchunks; i += ncta*256) {
            float4 v0 = ((const float4*)w2src)[2*i];
            float4 v1 = ((const float4*)w2src)[2*i + 1];
            uint4 o;
            o.x = pack2h(v0.x, v0.y); o.y = pack2h(v0.z, v0.w);
            o.z = pack2h(v1.x, v1.y); o.w = pack2h(v1.z, v1.w);
            ((uint4*)g_w2h)[i] = o;
        }
    }

    int tile = (MODE == 1) ? blockIdx.x : blockIdx.y;
    int nblk = (MODE == 1) ? blockIdx.y : blockIdx.x;
    if (tile >= g_num_tiles) return;
    int e    = g_tile_expert[tile];
    int row0 = g_tile_row0[tile];
    int m_valid = g_offsets[e+1] - row0;
    if (m_valid > BM) m_valid = BM;
    int n0 = nblk * BN;

    extern __shared__ uint32_t smem[];
    int* s_arow = (int*)(smem + OFF_AROW);

    const __half* Ah = (MODE == 1) ? g_xh : g_ih;
    const __half* We = ((MODE == 1) ? g_w13h : g_w2h)
                       + (size_t)e * ((MODE == 1) ? (size_t)2*INTER*KD : (size_t)HID*KD);

    for (int r = tid; r < BM; r += 256) {
        int gr = -1;
        if (r < m_valid) gr = (MODE == 1) ? g_perm_token[row0 + r] : (row0 + r);
        s_arow[r] = gr;
    }
    __syncthreads();

    int wid = tid >> 5, lane = tid & 31;
    int warp_m = wid >> 2, warp_n = wid & 3;       // 2 x 4 warps -> 64x32 warp tiles
    int g = lane >> 2, q = lane & 3;

    // ldmatrix per-lane invariant byte offsets (within a stage)
    int sub = lane & 7, sel = lane >> 3;
    uint32_t a_inv = (uint32_t)((warp_m*64 + (sel & 1)*8 + sub) * (PADP*4)
                                + (sel >> 1) * 16);
    uint32_t b_inv = (uint32_t)(A_STG*4
                                + (warp_n*32 + (sel >> 1)*8 + sub) * (PADP*4)
                                + (sel & 1) * 16);
    uint32_t smem_sb = (uint32_t)__cvta_generic_to_shared(smem);

    float acc[4][4][4];
    #pragma unroll
    for (int a = 0; a < 4; a++)
        #pragma unroll
        for (int b = 0; b < 4; b++)
            #pragma unroll
            for (int c = 0; c < 4; c++) acc[a][b][c] = 0.f;

    // ---- stage loader: A 512 16B-chunks (2/thr), B 512 (2/thr) ----
    auto load_stage = [&](int stage, int kt /*halves*/) {
        uint32_t* Ad = smem + stage*STG_U32;
        uint32_t* Bd = Ad + A_STG;
        #pragma unroll
        for (int i = 0; i < 2; i++) {
            int idx = tid + i*256;
            int r = idx >> 2, c = idx & 3;
            int gr = s_arow[r];
            const __half* src = Ah + (size_t)(gr < 0 ? 0 : gr) * KD + kt + c*8;
            cp16(Ad + r*PADP + c*4, src, gr >= 0);
        }
        #pragma unroll
        for (int i = 0; i < 2; i++) {
            int idx = tid + i*256;
            int r = idx >> 2, c = idx & 3;
            const __half* src = We + (size_t)(n0 + r) * KD + kt + c*8;
            cp16(Bd + r*PADP + c*4, src, true);
        }
        CP_COMMIT();
    };

    load_stage(0, 0);
    load_stage(1, BK);
    load_stage(2, 2*BK);

    for (int it = 0; it < KT; it++) {
        CP_WAIT2();            // <=2 groups outstanding -> stage it%4 arrived
        __syncthreads();       // all warps done with stage (it-1)%4 == (it+3)%4

        int nxt = it + 3;
        if (nxt < KT) load_stage(nxt % STAGES, nxt * BK);
        else CP_COMMIT();      // keep group accounting uniform

        uint32_t sb = smem_sb + (uint32_t)((it % STAGES) * (STG_U32*4));
        uint32_t a_base = sb + a_inv;
        uint32_t b_base = sb + b_inv;

        #pragma unroll
        for (int kk = 0; kk < 2; kk++) {           // two k16 halves
            uint32_t af[4][4], bf[4][2];
            #pragma unroll
            for (int mt = 0; mt < 4; mt++)
                ldsm4(af[mt], a_base + mt*(16*PADP*4) + kk*32);
            #pragma unroll
            for (int p = 0; p < 2; p++) {
                uint32_t r4[4];
                ldsm4(r4, b_base + p*(16*PADP*4) + kk*32);
                bf[2*p  ][0] = r4[0]; bf[2*p  ][1] = r4[1];
                bf[2*p+1][0] = r4[2]; bf[2*p+1][1] = r4[3];
            }
            #pragma unroll
            for (int mt = 0; mt < 4; mt++)
                #pragma unroll
                for (int nt = 0; nt < 4; nt++)
                    mma_f16(acc[mt][nt], af[mt], bf[nt]);
        }
    }

    // ---- epilogue ----
    #pragma unroll
    for (int mt = 0; mt < 4; mt++) {
        #pragma unroll
        for (int h = 0; h < 2; h++) {
            int lr = warp_m*64 + mt*16 + g + h*8;
            if (lr < m_valid) {
                int grow = row0 + lr;
                if (MODE == 1) {
                    // cols (2m,2m+1) = (gate,up) -> inter col m (fp16)
                    __half* dst = g_ih + (size_t)grow * INTER + (n0 >> 1) + warp_n*16;
                    #pragma unroll
                    for (int nt = 0; nt < 4; nt++) {
                        float gv = acc[mt][nt][h*2 + 0];
                        float uv = acc[mt][nt][h*2 + 1];
                        float iv = gv / (1.f + expf(-gv)) * uv;
                        dst[nt*4 + q] = __float2half_rn(iv);
                    }
                } else {
                    float sc = g_pair_w[grow];
                    __half* dst = g_pair_out + (size_t)grow * HID + n0 + warp_n*32;
                    #pragma unroll
                    for (int nt = 0; nt < 4; nt++) {
                        uint32_t packed = pack2h(acc[mt][nt][h*2 + 0] * sc,
                                                 acc[mt][nt][h*2 + 1] * sc);
                        *(uint32_t*)(dst + nt*8 + 2*q) = packed;
                    }
                }
            }
        }
    }
}

// ---------------- deterministic combine (fp16 inputs, fp32 output) ----------------
__global__ void combine_kernel(float* __restrict__ out) {
    int t = blockIdx.x;
    int p0 = g_pair_pos[t*4 + 0];
    int p1 = g_pair_pos[t*4 + 1];
    int p2 = g_pair_pos[t*4 + 2];
    int p3 = g_pair_pos[t*4 + 3];
    const __half2* r0 = (const __half2*)(g_pair_out + (size_t)p0 * HID);
    const __half2* r1 = (const __half2*)(g_pair_out + (size_t)p1 * HID);
    const __half2* r2 = (const __half2*)(g_pair_out + (size_t)p2 * HID);
    const __half2* r3 = (const __half2*)(g_pair_out + (size_t)p3 * HID);
    float2* o = (float2*)(out + (size_t)t * HID);
    for (int c = threadIdx.x; c < HID/2; c += blockDim.x) {
        float2 a = __half22float2(r0[c]);
        float2 b = __half22float2(r1[c]);
        float2 cc = __half22float2(r2[c]);
        float2 d = __half22float2(r3[c]);
        float2 v;
        v.x = a.x + b.x + cc.x + d.x;
        v.y = a.y + b.y + cc.y + d.y;
        o[c] = v;
    }
}

// ---------------- launch ----------------
extern "C" void kernel_launch(void* const* d_in, const int* in_sizes, int n_in,
                              void* d_out, int out_size) {
    const float* x      = (const float*)d_in[0];
    const float* logits = (const float*)d_in[1];
    const float* w13    = (const float*)d_in[2];
    const float* w2     = (const float*)d_in[3];
    float* out = (float*)d_out;

    cudaFuncSetAttribute((const void*)gemm_nt<1>,
                         cudaFuncAttributeMaxDynamicSharedMemorySize, SMEM_BYTES);
    cudaFuncSetAttribute((const void*)gemm_nt<2>,
                         cudaFuncAttributeMaxDynamicSharedMemorySize, SMEM_BYTES);

    zero_kernel<<<1, 32>>>();
    route_kernel<<<(NTOK + 255)/256, 256>>>(logits);
    scan_tiles_kernel<<<1, 1>>>();
    scatter_kernel<<<(NPAIR + 255)/256, 256>>>();

    // merged fp16 conversions: w13 (interleaved) + x. w2 moonlighted in GEMM1.
    {
        size_t total = NW13C + NXC;
        half_conv_kernel<<<(int)((total + 255)/256), 256>>>(w13, x);
    }

    gemm_nt<1><<<dim3(MAXTILES, (2*INTER)/BN), 256, SMEM_BYTES>>>(w2);
    gemm_nt<2><<<dim3(HID/BN, MAXTILES), 256, SMEM_BYTES>>>(nullptr);

    combine_kernel<<<NTOK, 128>>>(out);
}